// round 3
// baseline (speedup 1.0000x reference)
#include <cuda_runtime.h>

// Problem constants
#define Bq  4
#define Sq  2048
#define Dq  1024
#define Hq  16
#define HDq 64
#define Mq  (Bq * Sq)   // 8192 rows for projections

// Scratch for projected Q, K, V (allocation-free rule: device globals)
__device__ float g_q[(size_t)Mq * Dq];
__device__ float g_k[(size_t)Mq * Dq];
__device__ float g_v[(size_t)Mq * Dq];

// ============================================================================
// Fused QKV projection GEMM: C[m,n] = sum_k X[m,k] * W[n,k] + bias[n]
// blockIdx.z in {0,1,2} selects the (X, W, bias, C) tuple.
// 128x128 tile, BK=8, 256 threads, 8x8 micro-tile, k-major smem,
// double-buffered smem with register prefetch: ONE barrier per k-step,
// LDG for step i+1 issued before compute of step i (latency hidden).
// ============================================================================
__global__ __launch_bounds__(256) void gemm3_xwT_bias(
    const float* __restrict__ Xq, const float* __restrict__ Xk, const float* __restrict__ Xv,
    const float* __restrict__ Wq, const float* __restrict__ Wk, const float* __restrict__ Wv,
    const float* __restrict__ bq, const float* __restrict__ bk, const float* __restrict__ bv,
    float* __restrict__ Cq, float* __restrict__ Ck, float* __restrict__ Cv)
{
    __shared__ float As[2][8][128];
    __shared__ float Bs[2][8][128];

    const int z = blockIdx.z;
    const float* X    = (z == 0) ? Xq : (z == 1) ? Xk : Xv;
    const float* W    = (z == 0) ? Wq : (z == 1) ? Wk : Wv;
    const float* bias = (z == 0) ? bq : (z == 1) ? bk : bv;
    float*       C    = (z == 0) ? Cq : (z == 1) ? Ck : Cv;

    const int K = Dq, N = Dq;
    const int tid = threadIdx.x;
    const int tx  = tid & 15;
    const int ty  = tid >> 4;
    const int m0  = blockIdx.y * 128;
    const int n0  = blockIdx.x * 128;

    // load mapping: 128 rows x 8 k; 2 threads per row (k halves)
    const int lr = tid >> 1;
    const int lq = (tid & 1) * 4;

    const float* Xp = X + (size_t)(m0 + lr) * K + lq;
    const float* Wp = W + (size_t)(n0 + lr) * K + lq;

    float acc[8][8];
#pragma unroll
    for (int i = 0; i < 8; i++)
#pragma unroll
        for (int j = 0; j < 8; j++) acc[i][j] = 0.f;

    // preload tile 0 into buffer 0
    {
        float4 xv = *(const float4*)(Xp);
        float4 wv = *(const float4*)(Wp);
        As[0][lq + 0][lr] = xv.x; As[0][lq + 1][lr] = xv.y;
        As[0][lq + 2][lr] = xv.z; As[0][lq + 3][lr] = xv.w;
        Bs[0][lq + 0][lr] = wv.x; Bs[0][lq + 1][lr] = wv.y;
        Bs[0][lq + 2][lr] = wv.z; Bs[0][lq + 3][lr] = wv.w;
    }
    __syncthreads();

    int buf = 0;
    for (int k0 = 0; k0 < K; k0 += 8) {
        const bool has_next = (k0 + 8) < K;
        float4 nx, nw;
        if (has_next) {                       // prefetch next tile (latency hidden)
            nx = *(const float4*)(Xp + k0 + 8);
            nw = *(const float4*)(Wp + k0 + 8);
        }

#pragma unroll
        for (int kk = 0; kk < 8; kk++) {
            float4 a0 = *(const float4*)&As[buf][kk][ty * 4];
            float4 a1 = *(const float4*)&As[buf][kk][64 + ty * 4];
            float4 b0 = *(const float4*)&Bs[buf][kk][tx * 4];
            float4 b1 = *(const float4*)&Bs[buf][kk][64 + tx * 4];
            float ar[8] = {a0.x, a0.y, a0.z, a0.w, a1.x, a1.y, a1.z, a1.w};
            float br[8] = {b0.x, b0.y, b0.z, b0.w, b1.x, b1.y, b1.z, b1.w};
#pragma unroll
            for (int i = 0; i < 8; i++)
#pragma unroll
                for (int j = 0; j < 8; j++)
                    acc[i][j] += ar[i] * br[j];
        }

        if (has_next) {
            const int nb = buf ^ 1;
            As[nb][lq + 0][lr] = nx.x; As[nb][lq + 1][lr] = nx.y;
            As[nb][lq + 2][lr] = nx.z; As[nb][lq + 3][lr] = nx.w;
            Bs[nb][lq + 0][lr] = nw.x; Bs[nb][lq + 1][lr] = nw.y;
            Bs[nb][lq + 2][lr] = nw.z; Bs[nb][lq + 3][lr] = nw.w;
            __syncthreads();
            buf = nb;
        }
    }

    float4 bv0 = *(const float4*)(bias + n0 + tx * 4);
    float4 bv1 = *(const float4*)(bias + n0 + 64 + tx * 4);
    float bb[8] = {bv0.x, bv0.y, bv0.z, bv0.w, bv1.x, bv1.y, bv1.z, bv1.w};

#pragma unroll
    for (int i = 0; i < 8; i++) {
        int row = m0 + ((i < 4) ? (ty * 4 + i) : (64 + ty * 4 + i - 4));
        float4 o0, o1;
        o0.x = acc[i][0] + bb[0]; o0.y = acc[i][1] + bb[1];
        o0.z = acc[i][2] + bb[2]; o0.w = acc[i][3] + bb[3];
        o1.x = acc[i][4] + bb[4]; o1.y = acc[i][5] + bb[5];
        o1.z = acc[i][6] + bb[6]; o1.w = acc[i][7] + bb[7];
        *(float4*)(C + (size_t)row * N + n0 + tx * 4) = o0;
        *(float4*)(C + (size_t)row * N + n0 + 64 + tx * 4) = o1;
    }
}

// ============================================================================
// Flash attention (fp32, online softmax), 8x8 micro-tiles throughout.
// Grid (S/64, B*H), 128 threads/CTA. Bq=64 queries x Bk=128 keys per tile.
// Scores: thread (tx 0..15, ty 0..7) owns 8q x 8k. K smem quad-XOR swizzled.
// PV: k-range split across tx-halves; each thread 8q x 8d over its 64 keys;
// partial O pairs reduced through smem once at the epilogue.
// Dynamic smem 80KB: Qs[64*64] | KP[128*64] (K tile, then P[64][128]) | Vs[128*64]
// ============================================================================
__global__ __launch_bounds__(128) void flash_attn_kernel(float* __restrict__ out)
{
    extern __shared__ float smem[];
    float* Qs = smem;            // 4096 floats
    float* KP = smem + 4096;     // 8192 floats
    float* Vs = smem + 12288;    // 8192 floats

    const int tid = threadIdx.x;
    const int tx  = tid & 15;
    const int ty  = tid >> 4;        // 0..7
    const int txd = tx & 7;          // PV d-column group
    const int kg  = tx >> 3;         // PV k-half (0/1)
    const int qb  = blockIdx.x;
    const int bh  = blockIdx.y;
    const int b   = bh >> 4;         // H = 16
    const int h   = bh & 15;

    const size_t base = (size_t)(b * Sq) * Dq + h * HDq;
    const size_t qoff = base + (size_t)(qb * 64) * Dq;

    // tile-load mapping: 16 quad-columns x row groups
    const int lc = tid & 15;
    const int lg = tid >> 4;         // 0..7

    // Q tile [64][64], prescaled so softmax uses exp2 directly
    const float QSCALE = 0.125f * 1.4426950408889634f;
#pragma unroll
    for (int i = 0; i < 8; i++) {
        int r = lg * 8 + i;
        float4 v = *(const float4*)(g_q + qoff + (size_t)r * Dq + lc * 4);
        v.x *= QSCALE; v.y *= QSCALE; v.z *= QSCALE; v.w *= QSCALE;
        *(float4*)&Qs[r * 64 + lc * 4] = v;
    }

    int qrow[8];
#pragma unroll
    for (int i = 0; i < 8; i++)
        qrow[i] = (i < 4) ? (ty * 4 + i) : (32 + ty * 4 + i - 4);

    float m[8], l[8], O[8][8];
#pragma unroll
    for (int i = 0; i < 8; i++) {
        m[i] = -1e30f; l[i] = 0.f;
#pragma unroll
        for (int j = 0; j < 8; j++) O[i][j] = 0.f;
    }

    for (int kb = 0; kb < Sq / 128; kb++) {
        const size_t koff = base + (size_t)(kb * 128) * Dq;
        __syncthreads();   // previous iteration done with KP(P)/Vs

        // load K (swizzled) + V (plain): 128 rows, 16 per row-group
#pragma unroll
        for (int i = 0; i < 16; i++) {
            int r = lg * 16 + i;
            float4 kv = *(const float4*)(g_k + koff + (size_t)r * Dq + lc * 4);
            int cs = lc ^ ((r >> 2) & 15);
            *(float4*)&KP[r * 64 + cs * 4] = kv;
            float4 vv = *(const float4*)(g_v + koff + (size_t)r * Dq + lc * 4);
            *(float4*)&Vs[r * 64 + lc * 4] = vv;
        }
        __syncthreads();

        // --- scores: s[8q][8k] over 64 hd, float4 k-vectorized ---
        float s[8][8];
#pragma unroll
        for (int i = 0; i < 8; i++)
#pragma unroll
            for (int j = 0; j < 8; j++) s[i][j] = 0.f;

#pragma unroll
        for (int h4 = 0; h4 < 16; h4++) {
            float4 a[8], bf[8];
#pragma unroll
            for (int i = 0; i < 8; i++)
                a[i] = *(const float4*)&Qs[qrow[i] * 64 + h4 * 4];
            const int quad = (h4 ^ tx) * 4;   // swizzled read column
#pragma unroll
            for (int j = 0; j < 8; j++) {
                int k = (j < 4) ? (tx * 4 + j) : (64 + tx * 4 + j - 4);
                bf[j] = *(const float4*)&KP[k * 64 + quad];
            }
#pragma unroll
            for (int i = 0; i < 8; i++)
#pragma unroll
                for (int j = 0; j < 8; j++)
                    s[i][j] += a[i].x * bf[j].x + a[i].y * bf[j].y
                             + a[i].z * bf[j].z + a[i].w * bf[j].w;
        }

        // --- online softmax (base-2 domain); row stats over 16 tx lanes ---
#pragma unroll
        for (int i = 0; i < 8; i++) {
            float mx = s[i][0];
#pragma unroll
            for (int j = 1; j < 8; j++) mx = fmaxf(mx, s[i][j]);
            mx = fmaxf(mx, __shfl_xor_sync(0xffffffffu, mx, 1));
            mx = fmaxf(mx, __shfl_xor_sync(0xffffffffu, mx, 2));
            mx = fmaxf(mx, __shfl_xor_sync(0xffffffffu, mx, 4));
            mx = fmaxf(mx, __shfl_xor_sync(0xffffffffu, mx, 8));
            float mn   = fmaxf(m[i], mx);
            float corr = exp2f(m[i] - mn);
            float ps = 0.f;
#pragma unroll
            for (int j = 0; j < 8; j++) {
                s[i][j] = exp2f(s[i][j] - mn);
                ps += s[i][j];
            }
            ps += __shfl_xor_sync(0xffffffffu, ps, 1);
            ps += __shfl_xor_sync(0xffffffffu, ps, 2);
            ps += __shfl_xor_sync(0xffffffffu, ps, 4);
            ps += __shfl_xor_sync(0xffffffffu, ps, 8);
            l[i] = l[i] * corr + ps;
            m[i] = mn;
#pragma unroll
            for (int j = 0; j < 8; j++) O[i][j] *= corr;
        }

        __syncthreads();   // everyone done reading K from KP
        // write P row-major [64 q][128 k] over KP
#pragma unroll
        for (int i = 0; i < 8; i++) {
            int q = qrow[i];
            float4 p0 = make_float4(s[i][0], s[i][1], s[i][2], s[i][3]);
            float4 p1 = make_float4(s[i][4], s[i][5], s[i][6], s[i][7]);
            *(float4*)&KP[q * 128 + tx * 4]      = p0;
            *(float4*)&KP[q * 128 + 64 + tx * 4] = p1;
        }
        __syncthreads();

        // --- PV: each thread accumulates 8q x 8d over its 64-key half ---
        const int kbase = kg * 64;
#pragma unroll
        for (int k4 = 0; k4 < 16; k4++) {
            float4 a[8];
#pragma unroll
            for (int i = 0; i < 8; i++)
                a[i] = *(const float4*)&KP[qrow[i] * 128 + kbase + k4 * 4];
            float4 blo[4], bhi[4];
#pragma unroll
            for (int kk = 0; kk < 4; kk++) {
                int r = kbase + k4 * 4 + kk;
                blo[kk] = *(const float4*)&Vs[r * 64 + txd * 4];
                bhi[kk] = *(const float4*)&Vs[r * 64 + 32 + txd * 4];
            }
#pragma unroll
            for (int i = 0; i < 8; i++) {
                O[i][0] += a[i].x * blo[0].x + a[i].y * blo[1].x + a[i].z * blo[2].x + a[i].w * blo[3].x;
                O[i][1] += a[i].x * blo[0].y + a[i].y * blo[1].y + a[i].z * blo[2].y + a[i].w * blo[3].y;
                O[i][2] += a[i].x * blo[0].z + a[i].y * blo[1].z + a[i].z * blo[2].z + a[i].w * blo[3].z;
                O[i][3] += a[i].x * blo[0].w + a[i].y * blo[1].w + a[i].z * blo[2].w + a[i].w * blo[3].w;
                O[i][4] += a[i].x * bhi[0].x + a[i].y * bhi[1].x + a[i].z * bhi[2].x + a[i].w * bhi[3].x;
                O[i][5] += a[i].x * bhi[0].y + a[i].y * bhi[1].y + a[i].z * bhi[2].y + a[i].w * bhi[3].y;
                O[i][6] += a[i].x * bhi[0].z + a[i].y * bhi[1].z + a[i].z * bhi[2].z + a[i].w * bhi[3].z;
                O[i][7] += a[i].x * bhi[0].w + a[i].y * bhi[1].w + a[i].z * bhi[2].w + a[i].w * bhi[3].w;
            }
        }
    }

    // --- epilogue: reduce the two k-half partials, normalize, store ---
    __syncthreads();
    if (kg == 1) {
#pragma unroll
        for (int i = 0; i < 8; i++) {
            int q = qrow[i];
            *(float4*)&Qs[q * 64 + txd * 4]      = make_float4(O[i][0], O[i][1], O[i][2], O[i][3]);
            *(float4*)&Qs[q * 64 + 32 + txd * 4] = make_float4(O[i][4], O[i][5], O[i][6], O[i][7]);
        }
    }
    __syncthreads();
    if (kg == 0) {
#pragma unroll
        for (int i = 0; i < 8; i++) {
            int q = qrow[i];
            float inv = 1.f / l[i];
            float4 p0 = *(const float4*)&Qs[q * 64 + txd * 4];
            float4 p1 = *(const float4*)&Qs[q * 64 + 32 + txd * 4];
            float4 o0, o1;
            o0.x = (O[i][0] + p0.x) * inv; o0.y = (O[i][1] + p0.y) * inv;
            o0.z = (O[i][2] + p0.z) * inv; o0.w = (O[i][3] + p0.w) * inv;
            o1.x = (O[i][4] + p1.x) * inv; o1.y = (O[i][5] + p1.y) * inv;
            o1.z = (O[i][6] + p1.z) * inv; o1.w = (O[i][7] + p1.w) * inv;
            *(float4*)(out + qoff + (size_t)q * Dq + txd * 4)      = o0;
            *(float4*)(out + qoff + (size_t)q * Dq + 32 + txd * 4) = o1;
        }
    }
}

// ============================================================================
// Launch
// ============================================================================
extern "C" void kernel_launch(void* const* d_in, const int* in_sizes, int n_in,
                              void* d_out, int out_size)
{
    (void)in_sizes; (void)n_in; (void)out_size;
    const float* query = (const float*)d_in[0];
    const float* key   = (const float*)d_in[1];
    const float* value = (const float*)d_in[2];
    const float* Wq    = (const float*)d_in[3];
    const float* bqv   = (const float*)d_in[4];
    const float* Wk    = (const float*)d_in[5];
    const float* bkv   = (const float*)d_in[6];
    const float* Wv    = (const float*)d_in[7];
    const float* bvv   = (const float*)d_in[8];
    float* out = (float*)d_out;

    float *pq = nullptr, *pk = nullptr, *pv = nullptr;
    cudaGetSymbolAddress((void**)&pq, g_q);
    cudaGetSymbolAddress((void**)&pk, g_k);
    cudaGetSymbolAddress((void**)&pv, g_v);

    dim3 gGrid(Dq / 128, Mq / 128, 3);
    gemm3_xwT_bias<<<gGrid, 256>>>(query, key, value, Wq, Wk, Wv,
                                   bqv, bkv, bvv, pq, pk, pv);

    static const int ATTN_SMEM = 81920;  // 80KB dynamic shared
    cudaFuncSetAttribute(flash_attn_kernel,
                         cudaFuncAttributeMaxDynamicSharedMemorySize, ATTN_SMEM);
    dim3 aGrid(Sq / 64, Bq * Hq);
    flash_attn_kernel<<<aGrid, 128, ATTN_SMEM>>>(out);
}

// round 13
// speedup vs baseline: 2.4190x; 2.4190x over previous
#include <cuda_runtime.h>
#include <cstdint>

// Problem constants
#define Bq  4
#define Sq  2048
#define Dq  1024
#define Hq  16
#define HDq 64
#define Mq  (Bq * Sq)   // 8192 rows for projections

// Scratch for projected Q, K, V (allocation-free rule: device globals)
__device__ float g_q[(size_t)Mq * Dq];
__device__ float g_k[(size_t)Mq * Dq];
__device__ float g_v[(size_t)Mq * Dq];

__device__ __forceinline__ float ex2_approx(float x) {
    float r;
    asm("ex2.approx.ftz.f32 %0, %1;" : "=f"(r) : "f"(x));
    return r;
}

__device__ __forceinline__ float to_tf32(float x) {
    float r;
    asm("cvt.rna.tf32.f32 %0, %1;" : "=f"(r) : "f"(x));
    return r;
}

// ============================================================================
// Fused QKV projection GEMM on mma.sync tf32 tensor cores (target-portable PTX;
// tcgen05 is unavailable because the harness compiles PTX for plain sm_103).
// C[m,n] = sum_k X[m,k]*W[n,k] + bias[n]; blockIdx.z selects (X,W,bias,C).
// CTA: 128x128 tile, 256 threads = 8 warps (2 M x 4 N), warp tile 64x32,
// 16 x m16n8k8 MMA tiles per warp. BK=16, double-buffered smem.
// SMEM layout [row][k] with stride 20 words -> fragment LDS provably
// conflict-free (row*20 mod 32 covers all multiples of 4; +t4 fills quads).
// Inputs rounded to tf32 with cvt.rna at tile-store (zero-mean error).
// ============================================================================
__global__ __launch_bounds__(256) void gemm3_mma(
    const float* __restrict__ Xq, const float* __restrict__ Xk, const float* __restrict__ Xv,
    const float* __restrict__ Wq, const float* __restrict__ Wk, const float* __restrict__ Wv,
    const float* __restrict__ bq, const float* __restrict__ bk, const float* __restrict__ bv,
    float* __restrict__ Cq, float* __restrict__ Ck, float* __restrict__ Cv)
{
    __shared__ float As[2][128][20];   // 16 k + 4 pad
    __shared__ float Bs[2][128][20];

    const int z = blockIdx.z;
    const float* X    = (z == 0) ? Xq : (z == 1) ? Xk : Xv;
    const float* W    = (z == 0) ? Wq : (z == 1) ? Wk : Wv;
    const float* bias = (z == 0) ? bq : (z == 1) ? bk : bv;
    float*       C    = (z == 0) ? Cq : (z == 1) ? Ck : Cv;

    const int tid  = threadIdx.x;
    const int wid  = tid >> 5;
    const int lane = tid & 31;
    const int wr   = wid & 1;          // M half (64 rows)
    const int wc   = wid >> 1;         // N quarter (32 cols)
    const int g    = lane >> 2;        // group 0..7
    const int t4   = lane & 3;         // thread-in-group
    const int m0   = blockIdx.y * 128;
    const int n0   = blockIdx.x * 128;

    // loader mapping: 512 float4 slots per matrix per tile; 2 per thread
    const int r0 = tid >> 2,        q0 = tid & 3;
    const int r1 = (tid + 256) >> 2, q1 = (tid + 256) & 3;

    float acc[4][4][4];
#pragma unroll
    for (int i = 0; i < 4; i++)
#pragma unroll
        for (int j = 0; j < 4; j++)
#pragma unroll
            for (int c = 0; c < 4; c++) acc[i][j][c] = 0.f;

    // ---- preload chunk 0 into buffer 0 ----
    {
        float4 xa = *(const float4*)(X + (size_t)(m0 + r0) * Dq + q0 * 4);
        float4 xb = *(const float4*)(X + (size_t)(m0 + r1) * Dq + q1 * 4);
        float4 wa = *(const float4*)(W + (size_t)(n0 + r0) * Dq + q0 * 4);
        float4 wb = *(const float4*)(W + (size_t)(n0 + r1) * Dq + q1 * 4);
        As[0][r0][q0*4+0] = to_tf32(xa.x); As[0][r0][q0*4+1] = to_tf32(xa.y);
        As[0][r0][q0*4+2] = to_tf32(xa.z); As[0][r0][q0*4+3] = to_tf32(xa.w);
        As[0][r1][q1*4+0] = to_tf32(xb.x); As[0][r1][q1*4+1] = to_tf32(xb.y);
        As[0][r1][q1*4+2] = to_tf32(xb.z); As[0][r1][q1*4+3] = to_tf32(xb.w);
        Bs[0][r0][q0*4+0] = to_tf32(wa.x); Bs[0][r0][q0*4+1] = to_tf32(wa.y);
        Bs[0][r0][q0*4+2] = to_tf32(wa.z); Bs[0][r0][q0*4+3] = to_tf32(wa.w);
        Bs[0][r1][q1*4+0] = to_tf32(wb.x); Bs[0][r1][q1*4+1] = to_tf32(wb.y);
        Bs[0][r1][q1*4+2] = to_tf32(wb.z); Bs[0][r1][q1*4+3] = to_tf32(wb.w);
    }
    __syncthreads();

    for (int ch = 0; ch < Dq / 16; ch++) {
        const int buf = ch & 1;
        const bool has_next = (ch + 1) < (Dq / 16);
        float4 xa, xb, wa, wb;
        if (has_next) {
            const int k0 = (ch + 1) * 16;
            xa = *(const float4*)(X + (size_t)(m0 + r0) * Dq + k0 + q0 * 4);
            xb = *(const float4*)(X + (size_t)(m0 + r1) * Dq + k0 + q1 * 4);
            wa = *(const float4*)(W + (size_t)(n0 + r0) * Dq + k0 + q0 * 4);
            wb = *(const float4*)(W + (size_t)(n0 + r1) * Dq + k0 + q1 * 4);
        }

        // ---- compute on buf: 2 k-steps of 8, 16 MMA tiles each ----
#pragma unroll
        for (int ks = 0; ks < 16; ks += 8) {
            uint32_t af[4][4];
#pragma unroll
            for (int i = 0; i < 4; i++) {
                const int R0 = wr * 64 + i * 16;
                af[i][0] = __float_as_uint(As[buf][R0 + g    ][ks + t4    ]);
                af[i][1] = __float_as_uint(As[buf][R0 + g + 8][ks + t4    ]);
                af[i][2] = __float_as_uint(As[buf][R0 + g    ][ks + t4 + 4]);
                af[i][3] = __float_as_uint(As[buf][R0 + g + 8][ks + t4 + 4]);
            }
            uint32_t bf[4][2];
#pragma unroll
            for (int j = 0; j < 4; j++) {
                const int C0 = wc * 32 + j * 8;
                bf[j][0] = __float_as_uint(Bs[buf][C0 + g][ks + t4    ]);
                bf[j][1] = __float_as_uint(Bs[buf][C0 + g][ks + t4 + 4]);
            }
#pragma unroll
            for (int i = 0; i < 4; i++)
#pragma unroll
                for (int j = 0; j < 4; j++) {
                    asm volatile(
                        "mma.sync.aligned.m16n8k8.row.col.f32.tf32.tf32.f32 "
                        "{%0,%1,%2,%3}, {%4,%5,%6,%7}, {%8,%9}, {%0,%1,%2,%3};"
                        : "+f"(acc[i][j][0]), "+f"(acc[i][j][1]),
                          "+f"(acc[i][j][2]), "+f"(acc[i][j][3])
                        : "r"(af[i][0]), "r"(af[i][1]), "r"(af[i][2]), "r"(af[i][3]),
                          "r"(bf[j][0]), "r"(bf[j][1]));
                }
        }

        if (has_next) {
            const int nb = buf ^ 1;
            As[nb][r0][q0*4+0] = to_tf32(xa.x); As[nb][r0][q0*4+1] = to_tf32(xa.y);
            As[nb][r0][q0*4+2] = to_tf32(xa.z); As[nb][r0][q0*4+3] = to_tf32(xa.w);
            As[nb][r1][q1*4+0] = to_tf32(xb.x); As[nb][r1][q1*4+1] = to_tf32(xb.y);
            As[nb][r1][q1*4+2] = to_tf32(xb.z); As[nb][r1][q1*4+3] = to_tf32(xb.w);
            Bs[nb][r0][q0*4+0] = to_tf32(wa.x); Bs[nb][r0][q0*4+1] = to_tf32(wa.y);
            Bs[nb][r0][q0*4+2] = to_tf32(wa.z); Bs[nb][r0][q0*4+3] = to_tf32(wa.w);
            Bs[nb][r1][q1*4+0] = to_tf32(wb.x); Bs[nb][r1][q1*4+1] = to_tf32(wb.y);
            Bs[nb][r1][q1*4+2] = to_tf32(wb.z); Bs[nb][r1][q1*4+3] = to_tf32(wb.w);
            __syncthreads();
        }
    }

    // ---- epilogue: acc + bias -> C ----
#pragma unroll
    for (int j = 0; j < 4; j++) {
        const int col = n0 + wc * 32 + j * 8 + t4 * 2;
        const float b0 = bias[col], b1 = bias[col + 1];
#pragma unroll
        for (int i = 0; i < 4; i++) {
            const int row = m0 + wr * 64 + i * 16 + g;
            float2 lo = make_float2(acc[i][j][0] + b0, acc[i][j][1] + b1);
            float2 hi = make_float2(acc[i][j][2] + b0, acc[i][j][3] + b1);
            *(float2*)(C + (size_t)row * Dq + col)       = lo;
            *(float2*)(C + (size_t)(row + 8) * Dq + col) = hi;
        }
    }
}

// ============================================================================
// Flash attention (fp32, online softmax) — 256 threads/CTA for occupancy.
// Grid (S/64, B*H). Bq=64 queries x Bk=128 keys. Thread (tx 0..15, ty 0..15):
// scores 4q x 8k; PV 4q x 4d over full 128 keys (no split).
// Dynamic smem 80KB: Qs[64*64] | KP[128*64 K, then P 64x128] | Vs[128*64]
// ============================================================================
__global__ __launch_bounds__(256, 2) void flash_attn_kernel(float* __restrict__ out)
{
    extern __shared__ float smem[];
    float* Qs = smem;            // 4096 floats
    float* KP = smem + 4096;     // 8192 floats
    float* Vs = smem + 12288;    // 8192 floats

    const int tid = threadIdx.x;
    const int tx  = tid & 15;
    const int ty  = tid >> 4;        // 0..15
    const int qb  = blockIdx.x;
    const int bh  = blockIdx.y;
    const int b   = bh >> 4;         // H = 16
    const int h   = bh & 15;

    const size_t base = (size_t)(b * Sq) * Dq + h * HDq;
    const size_t qoff = base + (size_t)(qb * 64) * Dq;

    const int lc = tid & 15;         // quad-column for tile loads
    const int lg = tid >> 4;         // 0..15 row group

    // Q tile [64][64], prescaled so softmax uses exp2 directly
    const float QSCALE = 0.125f * 1.4426950408889634f;
#pragma unroll
    for (int i = 0; i < 4; i++) {
        int r = lg * 4 + i;
        float4 v = *(const float4*)(g_q + qoff + (size_t)r * Dq + lc * 4);
        v.x *= QSCALE; v.y *= QSCALE; v.z *= QSCALE; v.w *= QSCALE;
        *(float4*)&Qs[r * 64 + lc * 4] = v;
    }

    float m[4], l[4], O[4][4];
#pragma unroll
    for (int i = 0; i < 4; i++) {
        m[i] = -1e30f; l[i] = 0.f;
#pragma unroll
        for (int j = 0; j < 4; j++) O[i][j] = 0.f;
    }

    for (int kb = 0; kb < Sq / 128; kb++) {
        const size_t koff = base + (size_t)(kb * 128) * Dq;
        __syncthreads();   // previous iteration done with KP(P)/Vs

        // load K (swizzled) + V (plain): 128 rows, 8 per row-group
#pragma unroll
        for (int i = 0; i < 8; i++) {
            int r = lg * 8 + i;
            float4 kv = *(const float4*)(g_k + koff + (size_t)r * Dq + lc * 4);
            int cs = lc ^ ((r >> 2) & 15);
            *(float4*)&KP[r * 64 + cs * 4] = kv;
            float4 vv = *(const float4*)(g_v + koff + (size_t)r * Dq + lc * 4);
            *(float4*)&Vs[r * 64 + lc * 4] = vv;
        }
        __syncthreads();

        // --- scores: s[4q][8k] over 64 hd ---
        float s[4][8];
#pragma unroll
        for (int i = 0; i < 4; i++)
#pragma unroll
            for (int j = 0; j < 8; j++) s[i][j] = 0.f;

#pragma unroll
        for (int h4 = 0; h4 < 16; h4++) {
            float4 a[4], bf[8];
#pragma unroll
            for (int i = 0; i < 4; i++)
                a[i] = *(const float4*)&Qs[(ty * 4 + i) * 64 + h4 * 4];
            const int quad = (h4 ^ tx) * 4;   // swizzled read column
#pragma unroll
            for (int j = 0; j < 8; j++) {
                int k = (j < 4) ? (tx * 4 + j) : (64 + tx * 4 + j - 4);
                bf[j] = *(const float4*)&KP[k * 64 + quad];
            }
#pragma unroll
            for (int i = 0; i < 4; i++)
#pragma unroll
                for (int j = 0; j < 8; j++)
                    s[i][j] += a[i].x * bf[j].x + a[i].y * bf[j].y
                             + a[i].z * bf[j].z + a[i].w * bf[j].w;
        }

        // --- online softmax (base-2); row stats over 16 tx lanes ---
#pragma unroll
        for (int i = 0; i < 4; i++) {
            float mx = s[i][0];
#pragma unroll
            for (int j = 1; j < 8; j++) mx = fmaxf(mx, s[i][j]);
            mx = fmaxf(mx, __shfl_xor_sync(0xffffffffu, mx, 1));
            mx = fmaxf(mx, __shfl_xor_sync(0xffffffffu, mx, 2));
            mx = fmaxf(mx, __shfl_xor_sync(0xffffffffu, mx, 4));
            mx = fmaxf(mx, __shfl_xor_sync(0xffffffffu, mx, 8));
            float mn   = fmaxf(m[i], mx);
            float corr = ex2_approx(m[i] - mn);
            float ps = 0.f;
#pragma unroll
            for (int j = 0; j < 8; j++) {
                s[i][j] = ex2_approx(s[i][j] - mn);
                ps += s[i][j];
            }
            ps += __shfl_xor_sync(0xffffffffu, ps, 1);
            ps += __shfl_xor_sync(0xffffffffu, ps, 2);
            ps += __shfl_xor_sync(0xffffffffu, ps, 4);
            ps += __shfl_xor_sync(0xffffffffu, ps, 8);
            l[i] = l[i] * corr + ps;
            m[i] = mn;
#pragma unroll
            for (int j = 0; j < 4; j++) O[i][j] *= corr;
        }

        __syncthreads();   // everyone done reading K from KP
        // write P row-major [64 q][128 k] over KP
#pragma unroll
        for (int i = 0; i < 4; i++) {
            int q = ty * 4 + i;
            float4 p0 = make_float4(s[i][0], s[i][1], s[i][2], s[i][3]);
            float4 p1 = make_float4(s[i][4], s[i][5], s[i][6], s[i][7]);
            *(float4*)&KP[q * 128 + tx * 4]      = p0;
            *(float4*)&KP[q * 128 + 64 + tx * 4] = p1;
        }
        __syncthreads();

        // --- PV: each thread 4q x 4d over all 128 keys ---
#pragma unroll
        for (int k4 = 0; k4 < 32; k4++) {
            float4 a[4], bv[4];
#pragma unroll
            for (int i = 0; i < 4; i++)
                a[i] = *(const float4*)&KP[(ty * 4 + i) * 128 + k4 * 4];
#pragma unroll
            for (int kk = 0; kk < 4; kk++)
                bv[kk] = *(const float4*)&Vs[(k4 * 4 + kk) * 64 + tx * 4];
#pragma unroll
            for (int i = 0; i < 4; i++) {
                O[i][0] += a[i].x * bv[0].x + a[i].y * bv[1].x + a[i].z * bv[2].x + a[i].w * bv[3].x;
                O[i][1] += a[i].x * bv[0].y + a[i].y * bv[1].y + a[i].z * bv[2].y + a[i].w * bv[3].y;
                O[i][2] += a[i].x * bv[0].z + a[i].y * bv[1].z + a[i].z * bv[2].z + a[i].w * bv[3].z;
                O[i][3] += a[i].x * bv[0].w + a[i].y * bv[1].w + a[i].z * bv[2].w + a[i].w * bv[3].w;
            }
        }
    }

    // epilogue: normalize and store
#pragma unroll
    for (int i = 0; i < 4; i++) {
        int q = ty * 4 + i;
        float inv = 1.f / l[i];
        float4 o;
        o.x = O[i][0] * inv; o.y = O[i][1] * inv;
        o.z = O[i][2] * inv; o.w = O[i][3] * inv;
        *(float4*)(out + qoff + (size_t)q * Dq + tx * 4) = o;
    }
}

// ============================================================================
// Launch
// ============================================================================
extern "C" void kernel_launch(void* const* d_in, const int* in_sizes, int n_in,
                              void* d_out, int out_size)
{
    (void)in_sizes; (void)n_in; (void)out_size;
    const float* query = (const float*)d_in[0];
    const float* key   = (const float*)d_in[1];
    const float* value = (const float*)d_in[2];
    const float* Wq    = (const float*)d_in[3];
    const float* bqv   = (const float*)d_in[4];
    const float* Wk    = (const float*)d_in[5];
    const float* bkv   = (const float*)d_in[6];
    const float* Wv    = (const float*)d_in[7];
    const float* bvv   = (const float*)d_in[8];
    float* out = (float*)d_out;

    float *pq = nullptr, *pk = nullptr, *pv = nullptr;
    cudaGetSymbolAddress((void**)&pq, g_q);
    cudaGetSymbolAddress((void**)&pk, g_k);
    cudaGetSymbolAddress((void**)&pv, g_v);

    dim3 gGrid(Dq / 128, Mq / 128, 3);
    gemm3_mma<<<gGrid, 256>>>(query, key, value, Wq, Wk, Wv,
                              bqv, bkv, bvv, pq, pk, pv);

    static const int ATTN_SMEM = 81920;  // 80KB dynamic shared
    cudaFuncSetAttribute(flash_attn_kernel,
                         cudaFuncAttributeMaxDynamicSharedMemorySize, ATTN_SMEM);
    dim3 aGrid(Sq / 64, Bq * Hq);
    flash_attn_kernel<<<aGrid, 256, ATTN_SMEM>>>(out);
}

// round 14
// speedup vs baseline: 4.8220x; 1.9933x over previous
#include <cuda_runtime.h>
#include <cstdint>

// Problem constants
#define Bq  4
#define Sq  2048
#define Dq  1024
#define Hq  16
#define HDq 64
#define Mq  (Bq * Sq)   // 8192 rows for projections

// Scratch for projected Q, K, V (allocation-free rule: device globals)
__device__ float g_q[(size_t)Mq * Dq];
__device__ float g_k[(size_t)Mq * Dq];
__device__ float g_v[(size_t)Mq * Dq];

__device__ __forceinline__ float ex2_approx(float x) {
    float r;
    asm("ex2.approx.ftz.f32 %0, %1;" : "=f"(r) : "f"(x));
    return r;
}

__device__ __forceinline__ float to_tf32(float x) {
    float r;
    asm("cvt.rna.tf32.f32 %0, %1;" : "=f"(r) : "f"(x));
    return r;
}

#define MMA_TF32(d0,d1,d2,d3, a0,a1,a2,a3, b0,b1) \
    asm volatile( \
        "mma.sync.aligned.m16n8k8.row.col.f32.tf32.tf32.f32 " \
        "{%0,%1,%2,%3}, {%4,%5,%6,%7}, {%8,%9}, {%0,%1,%2,%3};" \
        : "+f"(d0), "+f"(d1), "+f"(d2), "+f"(d3) \
        : "r"(a0), "r"(a1), "r"(a2), "r"(a3), "r"(b0), "r"(b1))

// ============================================================================
// Fused QKV projection GEMM on mma.sync tf32 — byte-identical to the kernel
// measured passing in R13 (2135us total, rel_err 5.1e-4).
// ============================================================================
__global__ __launch_bounds__(256) void gemm3_mma(
    const float* __restrict__ Xq, const float* __restrict__ Xk, const float* __restrict__ Xv,
    const float* __restrict__ Wq, const float* __restrict__ Wk, const float* __restrict__ Wv,
    const float* __restrict__ bq, const float* __restrict__ bk, const float* __restrict__ bv,
    float* __restrict__ Cq, float* __restrict__ Ck, float* __restrict__ Cv)
{
    __shared__ float As[2][128][20];   // 16 k + 4 pad
    __shared__ float Bs[2][128][20];

    const int z = blockIdx.z;
    const float* X    = (z == 0) ? Xq : (z == 1) ? Xk : Xv;
    const float* W    = (z == 0) ? Wq : (z == 1) ? Wk : Wv;
    const float* bias = (z == 0) ? bq : (z == 1) ? bk : bv;
    float*       C    = (z == 0) ? Cq : (z == 1) ? Ck : Cv;

    const int tid  = threadIdx.x;
    const int wid  = tid >> 5;
    const int lane = tid & 31;
    const int wr   = wid & 1;
    const int wc   = wid >> 1;
    const int g    = lane >> 2;
    const int t4   = lane & 3;
    const int m0   = blockIdx.y * 128;
    const int n0   = blockIdx.x * 128;

    const int r0 = tid >> 2,        q0 = tid & 3;
    const int r1 = (tid + 256) >> 2, q1 = (tid + 256) & 3;

    float acc[4][4][4];
#pragma unroll
    for (int i = 0; i < 4; i++)
#pragma unroll
        for (int j = 0; j < 4; j++)
#pragma unroll
            for (int c = 0; c < 4; c++) acc[i][j][c] = 0.f;

    {
        float4 xa = *(const float4*)(X + (size_t)(m0 + r0) * Dq + q0 * 4);
        float4 xb = *(const float4*)(X + (size_t)(m0 + r1) * Dq + q1 * 4);
        float4 wa = *(const float4*)(W + (size_t)(n0 + r0) * Dq + q0 * 4);
        float4 wb = *(const float4*)(W + (size_t)(n0 + r1) * Dq + q1 * 4);
        As[0][r0][q0*4+0] = to_tf32(xa.x); As[0][r0][q0*4+1] = to_tf32(xa.y);
        As[0][r0][q0*4+2] = to_tf32(xa.z); As[0][r0][q0*4+3] = to_tf32(xa.w);
        As[0][r1][q1*4+0] = to_tf32(xb.x); As[0][r1][q1*4+1] = to_tf32(xb.y);
        As[0][r1][q1*4+2] = to_tf32(xb.z); As[0][r1][q1*4+3] = to_tf32(xb.w);
        Bs[0][r0][q0*4+0] = to_tf32(wa.x); Bs[0][r0][q0*4+1] = to_tf32(wa.y);
        Bs[0][r0][q0*4+2] = to_tf32(wa.z); Bs[0][r0][q0*4+3] = to_tf32(wa.w);
        Bs[0][r1][q1*4+0] = to_tf32(wb.x); Bs[0][r1][q1*4+1] = to_tf32(wb.y);
        Bs[0][r1][q1*4+2] = to_tf32(wb.z); Bs[0][r1][q1*4+3] = to_tf32(wb.w);
    }
    __syncthreads();

    for (int ch = 0; ch < Dq / 16; ch++) {
        const int buf = ch & 1;
        const bool has_next = (ch + 1) < (Dq / 16);
        float4 xa, xb, wa, wb;
        if (has_next) {
            const int k0 = (ch + 1) * 16;
            xa = *(const float4*)(X + (size_t)(m0 + r0) * Dq + k0 + q0 * 4);
            xb = *(const float4*)(X + (size_t)(m0 + r1) * Dq + k0 + q1 * 4);
            wa = *(const float4*)(W + (size_t)(n0 + r0) * Dq + k0 + q0 * 4);
            wb = *(const float4*)(W + (size_t)(n0 + r1) * Dq + k0 + q1 * 4);
        }

#pragma unroll
        for (int ks = 0; ks < 16; ks += 8) {
            uint32_t af[4][4];
#pragma unroll
            for (int i = 0; i < 4; i++) {
                const int R0 = wr * 64 + i * 16;
                af[i][0] = __float_as_uint(As[buf][R0 + g    ][ks + t4    ]);
                af[i][1] = __float_as_uint(As[buf][R0 + g + 8][ks + t4    ]);
                af[i][2] = __float_as_uint(As[buf][R0 + g    ][ks + t4 + 4]);
                af[i][3] = __float_as_uint(As[buf][R0 + g + 8][ks + t4 + 4]);
            }
            uint32_t bf[4][2];
#pragma unroll
            for (int j = 0; j < 4; j++) {
                const int C0 = wc * 32 + j * 8;
                bf[j][0] = __float_as_uint(Bs[buf][C0 + g][ks + t4    ]);
                bf[j][1] = __float_as_uint(Bs[buf][C0 + g][ks + t4 + 4]);
            }
#pragma unroll
            for (int i = 0; i < 4; i++)
#pragma unroll
                for (int j = 0; j < 4; j++)
                    MMA_TF32(acc[i][j][0], acc[i][j][1], acc[i][j][2], acc[i][j][3],
                             af[i][0], af[i][1], af[i][2], af[i][3],
                             bf[j][0], bf[j][1]);
        }

        if (has_next) {
            const int nb = buf ^ 1;
            As[nb][r0][q0*4+0] = to_tf32(xa.x); As[nb][r0][q0*4+1] = to_tf32(xa.y);
            As[nb][r0][q0*4+2] = to_tf32(xa.z); As[nb][r0][q0*4+3] = to_tf32(xa.w);
            As[nb][r1][q1*4+0] = to_tf32(xb.x); As[nb][r1][q1*4+1] = to_tf32(xb.y);
            As[nb][r1][q1*4+2] = to_tf32(xb.z); As[nb][r1][q1*4+3] = to_tf32(xb.w);
            Bs[nb][r0][q0*4+0] = to_tf32(wa.x); Bs[nb][r0][q0*4+1] = to_tf32(wa.y);
            Bs[nb][r0][q0*4+2] = to_tf32(wa.z); Bs[nb][r0][q0*4+3] = to_tf32(wa.w);
            Bs[nb][r1][q1*4+0] = to_tf32(wb.x); Bs[nb][r1][q1*4+1] = to_tf32(wb.y);
            Bs[nb][r1][q1*4+2] = to_tf32(wb.z); Bs[nb][r1][q1*4+3] = to_tf32(wb.w);
            __syncthreads();
        }
    }

#pragma unroll
    for (int j = 0; j < 4; j++) {
        const int col = n0 + wc * 32 + j * 8 + t4 * 2;
        const float b0 = bias[col], b1 = bias[col + 1];
#pragma unroll
        for (int i = 0; i < 4; i++) {
            const int row = m0 + wr * 64 + i * 16 + g;
            float2 lo = make_float2(acc[i][j][0] + b0, acc[i][j][1] + b1);
            float2 hi = make_float2(acc[i][j][2] + b0, acc[i][j][3] + b1);
            *(float2*)(C + (size_t)row * Dq + col)       = lo;
            *(float2*)(C + (size_t)(row + 8) * Dq + col) = hi;
        }
    }
}

// ============================================================================
// Flash attention on tf32 mma.sync tensor cores.
// Grid (S/64, B*H), 256 threads = 8 warps (wr = wid&1 -> 32 q rows,
// wc = wid>>2? no: wc = wid>>1 -> k/d column quarter).
// Scores: M=64 N=128 K=64(hd), warp tile 32x32, 8 MMAs x 8 k-steps.
// Softmax: fragment-local -> shfl over t4 -> cross-warp smem reduce (red).
// P (tf32-rounded) staged into K's smem buffer; PV: M=64 N=64(d) K=128,
// warp tile 32x16, 4 MMAs x 16 k-steps.
// Strides: Q/K/P  ≡ 4 (mod 32)  -> fragment bank 4g+t4  (conflict-free)
//          V = 72 ≡ 8 (mod 32)  -> fragment bank 8t4+g  (conflict-free)
// Dyn smem: Qs[64*68] | KP[max(128*68, 64*132)] | Vs[128*72] | red[4*64*2]
//         = (4352 + 8704 + 9216 + 512) * 4 = 91136 B -> 2 CTAs/SM.
// ============================================================================
#define A_SMEM_BYTES 91136

__global__ __launch_bounds__(256, 2) void flash_attn_mma(float* __restrict__ out)
{
    extern __shared__ float sm[];
    float* Qs  = sm;             // [64][68]
    float* KP  = sm + 4352;      // K [128][68], then P [64][132]
    float* Vs  = sm + 13056;     // [128][72]
    float* red = sm + 22272;     // [4 warpsets][64 rows][2]

    const int tid  = threadIdx.x;
    const int wid  = tid >> 5;
    const int lane = tid & 31;
    const int g    = lane >> 2;
    const int t4   = lane & 3;
    const int wr   = wid & 1;        // q half (32 rows)
    const int wc   = wid >> 1;       // col quarter
    const int qb   = blockIdx.x;
    const int bh   = blockIdx.y;
    const int b    = bh >> 4;        // H = 16
    const int h    = bh & 15;

    const size_t base = (size_t)(b * Sq) * Dq + h * HDq;
    const size_t qoff = base + (size_t)(qb * 64) * Dq;

    // ---- load Q tile [64][64], scaled + tf32 ----
    const float QSCALE = 0.125f * 1.4426950408889634f;
#pragma unroll
    for (int it = 0; it < 4; it++) {
        int f = tid + it * 256, r = f >> 4, c4 = f & 15;
        float4 v = *(const float4*)(g_q + qoff + (size_t)r * Dq + c4 * 4);
        v.x = to_tf32(v.x * QSCALE); v.y = to_tf32(v.y * QSCALE);
        v.z = to_tf32(v.z * QSCALE); v.w = to_tf32(v.w * QSCALE);
        *(float4*)&Qs[r * 68 + c4 * 4] = v;
    }

    float m[4], l[4], O[2][2][4];
#pragma unroll
    for (int x = 0; x < 4; x++) { m[x] = -1e30f; l[x] = 0.f; }
#pragma unroll
    for (int i = 0; i < 2; i++)
#pragma unroll
        for (int j = 0; j < 2; j++)
#pragma unroll
            for (int c = 0; c < 4; c++) O[i][j][c] = 0.f;

    for (int kb = 0; kb < Sq / 128; kb++) {
        const size_t koff = base + (size_t)(kb * 128) * Dq;
        __syncthreads();   // S0: prev iter done with KP(P)/Vs/red

        // ---- load K (tf32) and V (tf32) tiles ----
#pragma unroll
        for (int it = 0; it < 8; it++) {
            int f = tid + it * 256, r = f >> 4, c4 = f & 15;
            float4 kv = *(const float4*)(g_k + koff + (size_t)r * Dq + c4 * 4);
            kv.x = to_tf32(kv.x); kv.y = to_tf32(kv.y);
            kv.z = to_tf32(kv.z); kv.w = to_tf32(kv.w);
            *(float4*)&KP[r * 68 + c4 * 4] = kv;
            float4 vv = *(const float4*)(g_v + koff + (size_t)r * Dq + c4 * 4);
            vv.x = to_tf32(vv.x); vv.y = to_tf32(vv.y);
            vv.z = to_tf32(vv.z); vv.w = to_tf32(vv.w);
            *(float4*)&Vs[r * 72 + c4 * 4] = vv;
        }
        __syncthreads();   // S1: tiles visible

        // ---- scores: warp 32q x 32k, acc s[2][4][4] ----
        float s[2][4][4];
#pragma unroll
        for (int i = 0; i < 2; i++)
#pragma unroll
            for (int j = 0; j < 4; j++)
#pragma unroll
                for (int c = 0; c < 4; c++) s[i][j][c] = 0.f;

#pragma unroll
        for (int ks = 0; ks < 8; ks++) {
            uint32_t af[2][4];
#pragma unroll
            for (int i = 0; i < 2; i++) {
                const int R0 = wr * 32 + i * 16;
                af[i][0] = __float_as_uint(Qs[(R0 + g    ) * 68 + ks * 8 + t4    ]);
                af[i][1] = __float_as_uint(Qs[(R0 + g + 8) * 68 + ks * 8 + t4    ]);
                af[i][2] = __float_as_uint(Qs[(R0 + g    ) * 68 + ks * 8 + t4 + 4]);
                af[i][3] = __float_as_uint(Qs[(R0 + g + 8) * 68 + ks * 8 + t4 + 4]);
            }
            uint32_t bf[4][2];
#pragma unroll
            for (int j = 0; j < 4; j++) {
                const int C0 = wc * 32 + j * 8;
                bf[j][0] = __float_as_uint(KP[(C0 + g) * 68 + ks * 8 + t4    ]);
                bf[j][1] = __float_as_uint(KP[(C0 + g) * 68 + ks * 8 + t4 + 4]);
            }
#pragma unroll
            for (int i = 0; i < 2; i++)
#pragma unroll
                for (int j = 0; j < 4; j++)
                    MMA_TF32(s[i][j][0], s[i][j][1], s[i][j][2], s[i][j][3],
                             af[i][0], af[i][1], af[i][2], af[i][3],
                             bf[j][0], bf[j][1]);
        }

        // ---- pass1: per-warp row max -> red[wc][row][0] ----
#pragma unroll
        for (int i = 0; i < 2; i++)
#pragma unroll
            for (int ch = 0; ch < 2; ch++) {
                float mx = fmaxf(fmaxf(s[i][0][ch*2], s[i][0][ch*2+1]),
                                 fmaxf(s[i][1][ch*2], s[i][1][ch*2+1]));
                mx = fmaxf(mx, fmaxf(fmaxf(s[i][2][ch*2], s[i][2][ch*2+1]),
                                     fmaxf(s[i][3][ch*2], s[i][3][ch*2+1])));
                mx = fmaxf(mx, __shfl_xor_sync(0xffffffffu, mx, 1));
                mx = fmaxf(mx, __shfl_xor_sync(0xffffffffu, mx, 2));
                if (t4 == 0) {
                    int row = wr * 32 + i * 16 + ch * 8 + g;
                    red[(wc * 64 + row) * 2] = mx;
                }
            }
        __syncthreads();   // S2: red[0] visible; all warps done reading K

        float mn[4], corr[4];
#pragma unroll
        for (int i = 0; i < 2; i++)
#pragma unroll
            for (int ch = 0; ch < 2; ch++) {
                const int idx = i * 2 + ch;
                const int row = wr * 32 + i * 16 + ch * 8 + g;
                float gmax = fmaxf(fmaxf(red[(0*64+row)*2], red[(1*64+row)*2]),
                                   fmaxf(red[(2*64+row)*2], red[(3*64+row)*2]));
                mn[idx]   = fmaxf(m[idx], gmax);
                corr[idx] = ex2_approx(m[idx] - mn[idx]);
            }

        // ---- p = tf32(exp2(s-mn)); write P over KP; partial sums -> red[1] ----
        float lsum[4] = {0.f, 0.f, 0.f, 0.f};
#pragma unroll
        for (int i = 0; i < 2; i++)
#pragma unroll
            for (int j = 0; j < 4; j++)
#pragma unroll
                for (int c = 0; c < 4; c++) {
                    const int idx = i * 2 + (c >> 1);
                    float p = to_tf32(ex2_approx(s[i][j][c] - mn[idx]));
                    s[i][j][c] = p;
                    lsum[idx] += p;
                }
#pragma unroll
        for (int i = 0; i < 2; i++)
#pragma unroll
            for (int j = 0; j < 4; j++)
#pragma unroll
                for (int ch = 0; ch < 2; ch++) {
                    const int row = wr * 32 + i * 16 + ch * 8 + g;
                    const int col = wc * 32 + j * 8 + t4 * 2;
                    *(float2*)&KP[row * 132 + col] =
                        make_float2(s[i][j][ch*2], s[i][j][ch*2+1]);
                }
#pragma unroll
        for (int i = 0; i < 2; i++)
#pragma unroll
            for (int ch = 0; ch < 2; ch++) {
                const int idx = i * 2 + ch;
                float ps = lsum[idx];
                ps += __shfl_xor_sync(0xffffffffu, ps, 1);
                ps += __shfl_xor_sync(0xffffffffu, ps, 2);
                if (t4 == 0) {
                    int row = wr * 32 + i * 16 + ch * 8 + g;
                    red[(wc * 64 + row) * 2 + 1] = ps;
                }
            }
        __syncthreads();   // S3: P + red[1] visible

#pragma unroll
        for (int i = 0; i < 2; i++)
#pragma unroll
            for (int ch = 0; ch < 2; ch++) {
                const int idx = i * 2 + ch;
                const int row = wr * 32 + i * 16 + ch * 8 + g;
                float rs = red[(0*64+row)*2+1] + red[(1*64+row)*2+1]
                         + red[(2*64+row)*2+1] + red[(3*64+row)*2+1];
                l[idx] = l[idx] * corr[idx] + rs;
                m[idx] = mn[idx];
            }
#pragma unroll
        for (int i = 0; i < 2; i++)
#pragma unroll
            for (int j = 0; j < 2; j++)
#pragma unroll
                for (int c = 0; c < 4; c++)
                    O[i][j][c] *= corr[i * 2 + (c >> 1)];

        // ---- PV: warp 32q x 16d over 128 keys ----
#pragma unroll
        for (int ks = 0; ks < 16; ks++) {
            uint32_t af[2][4];
#pragma unroll
            for (int i = 0; i < 2; i++) {
                const int R0 = wr * 32 + i * 16;
                af[i][0] = __float_as_uint(KP[(R0 + g    ) * 132 + ks * 8 + t4    ]);
                af[i][1] = __float_as_uint(KP[(R0 + g + 8) * 132 + ks * 8 + t4    ]);
                af[i][2] = __float_as_uint(KP[(R0 + g    ) * 132 + ks * 8 + t4 + 4]);
                af[i][3] = __float_as_uint(KP[(R0 + g + 8) * 132 + ks * 8 + t4 + 4]);
            }
            uint32_t bf[2][2];
#pragma unroll
            for (int jn = 0; jn < 2; jn++) {
                const int C0 = wc * 16 + jn * 8;
                bf[jn][0] = __float_as_uint(Vs[(ks * 8 + t4    ) * 72 + C0 + g]);
                bf[jn][1] = __float_as_uint(Vs[(ks * 8 + t4 + 4) * 72 + C0 + g]);
            }
#pragma unroll
            for (int i = 0; i < 2; i++)
#pragma unroll
                for (int jn = 0; jn < 2; jn++)
                    MMA_TF32(O[i][jn][0], O[i][jn][1], O[i][jn][2], O[i][jn][3],
                             af[i][0], af[i][1], af[i][2], af[i][3],
                             bf[jn][0], bf[jn][1]);
        }
    }

    // ---- epilogue: normalize, store ----
#pragma unroll
    for (int i = 0; i < 2; i++)
#pragma unroll
        for (int ch = 0; ch < 2; ch++) {
            const int idx = i * 2 + ch;
            const int row = wr * 32 + i * 16 + ch * 8 + g;
            const float inv = 1.f / l[idx];
#pragma unroll
            for (int jn = 0; jn < 2; jn++) {
                const int col = wc * 16 + jn * 8 + t4 * 2;
                *(float2*)(out + qoff + (size_t)row * Dq + col) =
                    make_float2(O[i][jn][ch*2] * inv, O[i][jn][ch*2+1] * inv);
            }
        }
}

// ============================================================================
// Launch
// ============================================================================
extern "C" void kernel_launch(void* const* d_in, const int* in_sizes, int n_in,
                              void* d_out, int out_size)
{
    (void)in_sizes; (void)n_in; (void)out_size;
    const float* query = (const float*)d_in[0];
    const float* key   = (const float*)d_in[1];
    const float* value = (const float*)d_in[2];
    const float* Wq    = (const float*)d_in[3];
    const float* bqv   = (const float*)d_in[4];
    const float* Wk    = (const float*)d_in[5];
    const float* bkv   = (const float*)d_in[6];
    const float* Wv    = (const float*)d_in[7];
    const float* bvv   = (const float*)d_in[8];
    float* out = (float*)d_out;

    float *pq = nullptr, *pk = nullptr, *pv = nullptr;
    cudaGetSymbolAddress((void**)&pq, g_q);
    cudaGetSymbolAddress((void**)&pk, g_k);
    cudaGetSymbolAddress((void**)&pv, g_v);

    dim3 gGrid(Dq / 128, Mq / 128, 3);
    gemm3_mma<<<gGrid, 256>>>(query, key, value, Wq, Wk, Wv,
                              bqv, bkv, bvv, pq, pk, pv);

    cudaFuncSetAttribute(flash_attn_mma,
                         cudaFuncAttributeMaxDynamicSharedMemorySize, A_SMEM_BYTES);
    dim3 aGrid(Sq / 64, Bq * Hq);
    flash_attn_mma<<<aGrid, 256, A_SMEM_BYTES>>>(out);
}